// round 11
// baseline (speedup 1.0000x reference)
#include <cuda_runtime.h>
#include <cuda_fp16.h>
#include <stdint.h>

#define BB  4
#define AA  256
#define NN  64
#define NCB 128
#define NF  128
#define NSB 50

#define PITCH_A 136
#define IMG_A   (64 * PITCH_A * 2)        // 17408 B
#define ATOM_BLK (2 * IMG_A)              // 34816 (Ah, Vh)
#define WPITCH  72
#define IMG_WS  (128 * WPITCH * 2)        // 18432 B (one hi or lo slice image)
#define WSLICE  (2 * IMG_WS)              // 36864 B per slice buffer (hi+lo)
#define WB0     ATOM_BLK                  // 34816
#define WB1     (WB0 + WSLICE)            // 71680
#define SMEM_BYTES (WB1 + WSLICE)         // 108544
#define VPITCH  65
#define SLICE_HALVES 18432                // halves per slice in d_wsplit
#define STAGE_HALVES 36864

// ---------------- global scratch ----------------
__device__ __align__(16) float d_y[BB*AA*NF];
__device__ __align__(16) float d_vij[(size_t)BB*AA*NN*NCB];
__device__ __align__(16) float d_Vik[BB*AA*NCB*3];
__device__ __align__(16) __half d_wsplit[7 * STAGE_HALVES];

// ---------------- helpers ----------------
__device__ __forceinline__ void cp16(void* sdst, const void* gsrc) {
    unsigned s = (unsigned)__cvta_generic_to_shared(sdst);
    asm volatile("cp.async.cg.shared.global [%0], [%1], 16;" :: "r"(s), "l"(gsrc));
}
__device__ __forceinline__ void ldsm4(uint32_t* r, uint32_t saddr) {
    asm volatile("ldmatrix.sync.aligned.m8n8.x4.shared.b16 {%0,%1,%2,%3}, [%4];"
        : "=r"(r[0]), "=r"(r[1]), "=r"(r[2]), "=r"(r[3]) : "r"(saddr));
}
__device__ __forceinline__ void mma16816(float* c, const uint32_t* a,
                                         uint32_t b0, uint32_t b1) {
    asm volatile("mma.sync.aligned.m16n8k16.row.col.f32.f16.f16.f32 "
        "{%0,%1,%2,%3}, {%4,%5,%6,%7}, {%8,%9}, {%0,%1,%2,%3};"
        : "+f"(c[0]), "+f"(c[1]), "+f"(c[2]), "+f"(c[3])
        : "r"(a[0]), "r"(a[1]), "r"(a[2]), "r"(a[3]), "r"(b0), "r"(b1));
}
__device__ __forceinline__ void mma16816h(uint32_t* c, const uint32_t* a,
                                          uint32_t b0, uint32_t b1) {
    asm volatile("mma.sync.aligned.m16n8k16.row.col.f16.f16.f16.f16 "
        "{%0,%1}, {%2,%3,%4,%5}, {%6,%7}, {%0,%1};"
        : "+r"(c[0]), "+r"(c[1])
        : "r"(a[0]), "r"(a[1]), "r"(a[2]), "r"(a[3]), "r"(b0), "r"(b1));
}
__device__ __forceinline__ float sspf(float x) {
    if (x > 15.f) return x - 0.69314718055994531f;
    return __logf(1.f + __expf(x)) - 0.69314718055994531f;
}
__device__ __forceinline__ uint32_t smem_u32(const void* p) {
    return (uint32_t)__cvta_generic_to_shared(p);
}
__device__ __forceinline__ void mbar_wait(uint32_t mb, uint32_t parity) {
    uint32_t done;
    asm volatile("{\n\t.reg .pred p;\n\t"
        "mbarrier.try_wait.parity.acquire.cta.shared::cta.b64 p, [%1], %2;\n\t"
        "selp.b32 %0, 1, 0, p;\n\t}"
        : "=r"(done) : "r"(mb), "r"(parity) : "memory");
    if (!done) {
        asm volatile("{\n\t.reg .pred P1;\n\t"
            "W_%=:\n\t"
            "mbarrier.try_wait.parity.acquire.cta.shared::cta.b64 P1, [%0], %1, 0x989680;\n\t"
            "@P1 bra.uni D_%=;\n\t"
            "bra.uni W_%=;\n\t"
            "D_%=:\n\t}"
            :: "r"(mb), "r"(parity) : "memory");
    }
}

// ---------------- kernel: weight prep (blocks 0-6) + embedding (rest) -------
__global__ void __launch_bounds__(512) k_init(
    const float* fW1, const float* fW2, const float* f2oW,
    const float* pW1, const float* pW2, const float* eW1, const float* eW2,
    const float* __restrict__ xi, const float* __restrict__ in2f_W) {
    extern __shared__ float sdyn[];
    int bid = blockIdx.x;
    int tid = threadIdx.x;
    if (bid < 7) {
        const float* W; int K, realK;
        switch (bid) {
            case 0: W = fW1;  K = 64;  realK = NSB; break;
            case 1: W = fW2;  K = 128; realK = 128; break;
            case 2: W = f2oW; K = 128; realK = 128; break;
            case 3: W = pW1;  K = 128; realK = 128; break;
            case 4: W = pW2;  K = 128; realK = 128; break;
            case 5: W = eW1;  K = 128; realK = 128; break;
            default: W = eW2; K = 128; realK = 128; break;
        }
        __half* base = d_wsplit + (size_t)bid * STAGE_HALVES;
        for (int i = tid; i < 128 * K; i += 512) {
            int n = i / K, k = i - (i / K) * K;
            float v = (k < realK) ? W[k * 128 + n] : 0.f;   // B^T: [n][k]
            __half h = __float2half_rn(v);
            int sl = k >> 6, kk = k & 63;
            __half* hi = base + sl * SLICE_HALVES + n * WPITCH + kk;
            hi[0]    = h;
            hi[9216] = __float2half_rn(v - __half2float(h));   // lo image
        }
    } else {
        // embedding: 32 rows per block, W staged to smem
        float* sW = sdyn;                  // [128][128] f32, 64KB
        float* sx = sdyn + 128 * 128;      // [32][132]
        int row0 = (bid - 7) * 32;
        for (int i = tid * 4; i < 128 * 128; i += 512 * 4)
            cp16(sW + i, in2f_W + i);
        asm volatile("cp.async.commit_group;" ::: "memory");
        for (int i = tid; i < 32 * 128; i += 512) {
            int r = i >> 7, c = i & 127;
            sx[r * 132 + c] = xi[(size_t)(row0 + r) * 128 + c];
        }
        asm volatile("cp.async.wait_group 0;" ::: "memory");
        __syncthreads();
        int r  = tid >> 4;            // 0..31
        int c0 = (tid & 15) * 8;      // 0..120
        float acc[8];
        #pragma unroll
        for (int j = 0; j < 8; j++) acc[j] = 0.f;
        #pragma unroll 4
        for (int k = 0; k < 128; k++) {
            float a = sx[r * 132 + k];
            float4 w0 = *reinterpret_cast<const float4*>(sW + k * 128 + c0);
            float4 w1 = *reinterpret_cast<const float4*>(sW + k * 128 + c0 + 4);
            acc[0] = fmaf(a, w0.x, acc[0]); acc[1] = fmaf(a, w0.y, acc[1]);
            acc[2] = fmaf(a, w0.z, acc[2]); acc[3] = fmaf(a, w0.w, acc[3]);
            acc[4] = fmaf(a, w1.x, acc[4]); acc[5] = fmaf(a, w1.y, acc[5]);
            acc[6] = fmaf(a, w1.z, acc[6]); acc[7] = fmaf(a, w1.w, acc[7]);
        }
        float* dst = d_y + (size_t)(row0 + r) * 128 + c0;
        *reinterpret_cast<float4*>(dst)     = make_float4(acc[0], acc[1], acc[2], acc[3]);
        *reinterpret_cast<float4*>(dst + 4) = make_float4(acc[4], acc[5], acc[6], acc[7]);
    }
}

// 2-product GEMM over one K=64 slice (4 ksteps)
__device__ __forceinline__ void mm4(uint32_t aBase, uint32_t wBase,
                                    float (&acc)[8][4], uint32_t (&accL)[8][2],
                                    int lw, int lane, int kOffB) {
    const int warp_m = lw >> 2, warp_n = lw & 3;
    const int rsel = lane & 15, hsel = lane >> 4;
    uint32_t aAddr = aBase + (uint32_t)(((warp_m*32 + rsel) * PITCH_A + hsel*8) * 2) + kOffB;
    uint32_t wAddr = wBase + (uint32_t)(((warp_n*32 + rsel) * WPITCH + hsel*8) * 2);
    const uint32_t SA = 16 * PITCH_A * 2;
    const uint32_t SW = 16 * WPITCH * 2;
    #pragma unroll
    for (int kk = 0; kk < 4; kk++) {
        uint32_t A[2][4], Wh[2][4], Wl[2][4];
        uint32_t ak = aAddr + kk * 32;
        uint32_t wk = wAddr + kk * 32;
        ldsm4(A[0], ak);
        ldsm4(A[1], ak + SA);
        ldsm4(Wh[0], wk);
        ldsm4(Wh[1], wk + SW);
        ldsm4(Wl[0], wk + IMG_WS);
        ldsm4(Wl[1], wk + IMG_WS + SW);
        #pragma unroll
        for (int mt = 0; mt < 2; mt++)
            #pragma unroll
            for (int q = 0; q < 2; q++)
                #pragma unroll
                for (int j = 0; j < 2; j++) {
                    int t = mt*4 + q*2 + j;
                    mma16816(acc[t],  A[mt], Wh[q][j], Wh[q][j+2]);
                    mma16816h(accL[t], A[mt], Wl[q][j], Wl[q][j+2]);
                }
    }
}

// stage epilogue (one atom, 64 rows)
__device__ __forceinline__ void epilogue(
    int s, float (&acc)[8][4], uint32_t (&accL)[8][2], char* smem, int ba,
    int lw, int lane,
    const float* __restrict__ bias,
    const float* sCut, const int* sNbr)
{
    const int warp_m = lw >> 2, warp_n = lw & 3;
    const int er = lane >> 2, ec2 = (lane & 3) * 2;
    char* dstH = smem + ((s == 2) ? IMG_A : 0);
    float* vikT = reinterpret_cast<float*>(smem + WB0);
    const int bA = ba >> 8;
    #pragma unroll
    for (int mt = 0; mt < 2; mt++) {
        #pragma unroll
        for (int nt = 0; nt < 4; nt++) {
            int t = mt*4 + nt;
            int col = warp_n*32 + nt*8 + ec2;
            float b0 = __ldg(bias + col), b1 = __ldg(bias + col + 1);
            #pragma unroll
            for (int h = 0; h < 2; h++) {
                int row = warp_m*32 + mt*16 + er + h*8;   // 0..63
                __half2 lo2 = *reinterpret_cast<__half2*>(&accL[t][h]);
                float x0 = acc[t][h*2+0] + __half2float(lo2.x) + b0;
                float x1 = acc[t][h*2+1] + __half2float(lo2.y) + b1;
                if (s == 1) {
                    float cu = sCut[row];
                    const float2 y = *reinterpret_cast<const float2*>(
                        d_y + ((size_t)((bA << 8) + sNbr[row]) << 7) + col);
                    x0 = x0 * cu * y.x;
                    x1 = x1 * cu * y.y;
                } else if (s == 4) {
                    *reinterpret_cast<float2*>(
                        d_vij + ((size_t)ba * 64 + row) * 128 + col) =
                        make_float2(x0, x1);
                    continue;
                } else if (s == 6) {
                    vikT[col * VPITCH + row]       = x0;
                    vikT[(col + 1) * VPITCH + row] = x1;
                    continue;
                } else {
                    x0 = sspf(x0); x1 = sspf(x1);
                }
                __half2 hp = __floats2half2_rn(x0, x1);
                uint32_t off = (uint32_t)(row * PITCH_A + col) * 2;
                *reinterpret_cast<uint32_t*>(dstH + off) = *reinterpret_cast<uint32_t*>(&hp);
            }
        }
    }
}

// slice j -> (stage, half)
__device__ __forceinline__ int slice_stage(int j) { return (j + 1) >> 1; }
__device__ __forceinline__ int slice_half(int j)  { return j == 0 ? 0 : ((j + 1) & 1); }

// ---------------- kernel: fused interaction, 1 atom/CTA, 2 CTAs/SM ---------
__global__ void __launch_bounds__(256, 2) k_main(
    const float* __restrict__ r_ij, const float* __restrict__ cos_ij,
    const float* __restrict__ f_ij, const float* __restrict__ nmask,
    const float* __restrict__ fb1, const float* __restrict__ fb2,
    const float* __restrict__ f2ob,
    const float* __restrict__ aW1, const float* __restrict__ ab1,
    const float* __restrict__ aW2, const float* __restrict__ ab2,
    const float* __restrict__ pb1, const float* __restrict__ pb2,
    const float* __restrict__ eb1, const float* __restrict__ eb2,
    const int* __restrict__ neighbors, float* __restrict__ out_vi)
{
    extern __shared__ char smem[];
    const uint32_t sb = smem_u32(smem);
    const int tid = threadIdx.x, lw = tid >> 5, lane = tid & 31;
    const int ba = blockIdx.x;

    __shared__ float sCut[64], sMask[64], cmS[192], vsumS[128], hidS[128];
    __shared__ int   sNbr[64];
    __shared__ __align__(8) uint64_t mbarW[2];
    const uint32_t mbar0 = smem_u32(&mbarW[0]);
    const uint32_t mbar1 = smem_u32(&mbarW[1]);

    if (tid == 0) {
        asm volatile("mbarrier.init.shared.b64 [%0], %1;" :: "r"(mbar0), "r"(256u) : "memory");
        asm volatile("mbarrier.init.shared.b64 [%0], %1;" :: "r"(mbar1), "r"(256u) : "memory");
    }
    if (tid < 64) {
        int g = ba * NN + tid;
        float r = r_ij[g];
        sCut[tid]  = (r < 5.f) ? 0.5f * (__cosf(r * 0.62831853071795864f) + 1.f) : 0.f;
        float m = nmask[g];
        sMask[tid] = m;
        sNbr[tid]  = neighbors[g];
        cmS[tid*3+0] = cos_ij[(size_t)g*3+0] * m;
        cmS[tid*3+1] = cos_ij[(size_t)g*3+1] * m;
        cmS[tid*3+2] = cos_ij[(size_t)g*3+2] * m;
    }
    {   // zero Ah image
        uint64_t* z = reinterpret_cast<uint64_t*>(smem);
        for (int i = tid; i < IMG_A/8; i += 256) z[i] = 0ull;
    }
    __syncthreads();

    // issue slice 0 -> B0, slice 1 -> B1
    {
        const char* src0 = reinterpret_cast<const char*>(d_wsplit);            // s0 h0
        for (int i = tid * 16; i < WSLICE; i += 256*16)
            cp16(smem + WB0 + i, src0 + i);
        asm volatile("cp.async.mbarrier.arrive.noinc.shared.b64 [%0];" :: "r"(mbar0) : "memory");
        const char* src1 = reinterpret_cast<const char*>(d_wsplit + STAGE_HALVES); // s1 h0
        for (int i = tid * 16; i < WSLICE; i += 256*16)
            cp16(smem + WB1 + i, src1 + i);
        asm volatile("cp.async.mbarrier.arrive.noinc.shared.b64 [%0];" :: "r"(mbar1) : "memory");
    }
    {   // scatter features (fp16) into Ah
        const float* fg = f_ij + (size_t)ba * NN * NSB;
        __half* ah = reinterpret_cast<__half*>(smem);
        for (int i = tid; i < NN * NSB; i += 256) {
            int r = i / NSB, c = i - (i / NSB) * NSB;
            ah[r * PITCH_A + c] = __float2half_rn(fg[i]);
        }
    }
    __syncthreads();

    const float* biases[7] = {fb1, fb2, f2ob, pb1, pb2, eb1, eb2};
    float acc[8][4];
    uint32_t accL[8][2];
    int j = 0;   // global slice index 0..12

    for (int s = 0; s < 7; s++) {
        #pragma unroll
        for (int t = 0; t < 8; t++) {
            #pragma unroll
            for (int q = 0; q < 4; q++) acc[t][q] = 0.f;
            accL[t][0] = 0u; accL[t][1] = 0u;
        }
        const uint32_t aBase = sb + ((s == 3 || s == 5) ? IMG_A : 0);
        const int nslices = (s == 0) ? 1 : 2;

        for (int h = 0; h < nslices; h++, j++) {
            mbar_wait((j & 1) ? mbar1 : mbar0, (uint32_t)((j >> 1) & 1));
            mm4(aBase, sb + ((j & 1) ? WB1 : WB0), acc, accL, lw, lane,
                slice_half(j) * 128);
            __syncthreads();    // everyone done with buffer j&1 (and A image)
            int jn = j + 2;
            if (jn <= 12) {     // refill this buffer with slice jn
                int ss = slice_stage(jn), hh = slice_half(jn);
                const char* src = reinterpret_cast<const char*>(
                    d_wsplit + (size_t)ss * STAGE_HALVES + (size_t)hh * SLICE_HALVES);
                uint32_t woff = (jn & 1) ? WB1 : WB0;
                for (int i = tid * 16; i < WSLICE; i += 256*16)
                    cp16(smem + woff + i, src + i);
                asm volatile("cp.async.mbarrier.arrive.noinc.shared.b64 [%0];"
                             :: "r"((jn & 1) ? mbar1 : mbar0) : "memory");
            }
        }

        epilogue(s, acc, accL, smem, ba, lw, lane, biases[s], sCut, sNbr);
        __syncthreads();   // epilogue writes visible before next stage's ldsm
    }

    // ---- Vik[c][d] = sum_n vik[n][c] * cm[n][d] ----
    {
        const float* vikT = reinterpret_cast<const float*>(smem + WB0);
        for (int e = tid; e < 384; e += 256) {
            int c = e / 3, d = e - 3 * (e / 3);
            float s = 0.f;
            #pragma unroll 4
            for (int n = 0; n < 64; n++)
                s = fmaf(vikT[c * VPITCH + n], cmS[n * 3 + d], s);
            d_Vik[(size_t)ba * 384 + e] = s;
        }
    }

    // ---- vsum from V (fp16 image), atom MLP -> out_vi ----
    if (tid < 128) {
        const __half* vh = reinterpret_cast<const __half*>(smem + IMG_A);
        float s = 0.f;
        #pragma unroll 4
        for (int n = 0; n < 64; n++)
            s = fmaf(__half2float(vh[n * PITCH_A + tid]), sMask[n], s);
        vsumS[tid] = s;
    }
    __syncthreads();
    if (tid < 128) {
        float h = __ldg(ab1 + tid);
        #pragma unroll 4
        for (int k = 0; k < 128; k++)
            h = fmaf(vsumS[k], __ldg(aW1 + k * 128 + tid), h);
        hidS[tid] = sspf(h);
    }
    __syncthreads();
    if (tid < 128) {
        float o = __ldg(ab2 + tid);
        #pragma unroll 4
        for (int k = 0; k < 128; k++)
            o = fmaf(hidS[k], __ldg(aW2 + k * 128 + tid), o);
        out_vi[(size_t)ba * NF + tid] = o;
    }
}

// ---------------- kernel: assemble V (direct, float4) ----------------
__global__ void __launch_bounds__(96) k_assemble(
    const float* __restrict__ cos_ij,
    const int* __restrict__ neighbors,
    float* __restrict__ outV) {
    int idx = blockIdx.x;            // (b,a,n) flat
    int tid = threadIdx.x;           // 0..95
    int ba  = idx >> 6;
    int b   = idx >> 14;
    int nb  = __ldg(neighbors + idx);
    int e0  = tid * 4;
    int c0  = e0 / 3;

    float4 vl = *reinterpret_cast<const float4*>(d_Vik + (size_t)ba * 384 + e0);
    float4 vn = *reinterpret_cast<const float4*>(
        d_Vik + ((size_t)(b * AA + nb)) * 384 + e0);
    float cc[3];
    cc[0] = __ldg(cos_ij + (size_t)idx * 3 + 0);
    cc[1] = __ldg(cos_ij + (size_t)idx * 3 + 1);
    cc[2] = __ldg(cos_ij + (size_t)idx * 3 + 2);
    float vij0 = __ldg(d_vij + (size_t)idx * 128 + c0);
    float vij1 = __ldg(d_vij + (size_t)idx * 128 + c0 + 1);

    float vls[4] = {vl.x, vl.y, vl.z, vl.w};
    float vns[4] = {vn.x, vn.y, vn.z, vn.w};
    float4 o;
    float* op = reinterpret_cast<float*>(&o);
    #pragma unroll
    for (int jj = 0; jj < 4; jj++) {
        int e = e0 + jj;
        int c = e / 3, d = e - 3 * c;
        float vij = (c == c0) ? vij0 : vij1;
        op[jj] = fmaf(vij, cc[d], vls[jj] + vns[jj]);
    }
    *reinterpret_cast<float4*>(outV + (size_t)idx * 384 + e0) = o;
}

// ---------------- launch ----------------
extern "C" void kernel_launch(void* const* d_in, const int* in_sizes, int n_in,
                              void* d_out, int out_size) {
    const float* xi       = (const float*)d_in[0];
    const float* r_ij     = (const float*)d_in[1];
    const float* cos_ij   = (const float*)d_in[2];
    const float* f_ij     = (const float*)d_in[3];
    const float* nmask    = (const float*)d_in[4];
    const float* fW1      = (const float*)d_in[5];
    const float* fb1      = (const float*)d_in[6];
    const float* fW2      = (const float*)d_in[7];
    const float* fb2      = (const float*)d_in[8];
    const float* in2f_W   = (const float*)d_in[9];
    const float* f2oW     = (const float*)d_in[10];
    const float* f2ob     = (const float*)d_in[11];
    const float* aW1      = (const float*)d_in[12];
    const float* ab1      = (const float*)d_in[13];
    const float* aW2      = (const float*)d_in[14];
    const float* ab2      = (const float*)d_in[15];
    const float* pW1      = (const float*)d_in[16];
    const float* pb1      = (const float*)d_in[17];
    const float* pW2      = (const float*)d_in[18];
    const float* pb2      = (const float*)d_in[19];
    const float* eW1      = (const float*)d_in[20];
    const float* eb1      = (const float*)d_in[21];
    const float* eW2      = (const float*)d_in[22];
    const float* eb2      = (const float*)d_in[23];
    const int*   neighbors= (const int*)d_in[24];

    float* out = (float*)d_out;
    float* out_vi = out;                          // [B,A,NCB]
    float* out_V  = out + (size_t)BB*AA*NCB;      // [B,A,N,NCB,3]

    static const int INIT_SMEM = (128*128 + 32*132) * (int)sizeof(float);  // 82432
    cudaFuncSetAttribute(k_init, cudaFuncAttributeMaxDynamicSharedMemorySize, INIT_SMEM);
    cudaFuncSetAttribute(k_main, cudaFuncAttributeMaxDynamicSharedMemorySize,
                         (int)SMEM_BYTES);

    k_init<<<7 + BB*AA/32, 512, INIT_SMEM>>>(fW1, fW2, f2oW, pW1, pW2, eW1, eW2, xi, in2f_W);
    k_main<<<BB*AA, 256, SMEM_BYTES>>>(
        r_ij, cos_ij, f_ij, nmask,
        fb1, fb2, f2ob, aW1, ab1, aW2, ab2,
        pb1, pb2, eb1, eb2, neighbors, out_vi);
    k_assemble<<<BB*AA*NN, 96>>>(cos_ij, neighbors, out_V);
}

// round 12
// speedup vs baseline: 1.0989x; 1.0989x over previous
#include <cuda_runtime.h>
#include <cuda_fp16.h>
#include <stdint.h>

#define BB  4
#define AA  256
#define NN  64
#define NCB 128
#define NF  128
#define NSB 50

#define PITCH 136
#define IMG_A (64 * PITCH * 2)          // 17408
#define IMG_W (128 * PITCH * 2)         // 34816
#define ATOM_BLK (2 * IMG_A)            // 34816 (Ah, Vh per atom)
#define WBUF (2 * IMG_W)                // 69632 (hi + lo)
#define W0_OFF (2 * ATOM_BLK)           // 69632
#define W1_OFF (W0_OFF + WBUF)          // 139264
#define SMEM_BYTES (W1_OFF + WBUF)      // 208896
#define VPITCH 65
#define INIT_SMEM (IMG_A + 2 * IMG_W)   // 87040 (Ah + Wh + Wl)

// ---------------- global scratch ----------------
__device__ __align__(16) float d_y[BB*AA*NF];
__device__ __align__(16) float d_vij[(size_t)BB*AA*NN*NCB];
__device__ __align__(16) float d_Vik[BB*AA*NCB*3];
__device__ __align__(16) __half d_wsplit[7 * 2 * 128 * PITCH];

// ---------------- helpers ----------------
__device__ __forceinline__ void cp16(void* sdst, const void* gsrc) {
    unsigned s = (unsigned)__cvta_generic_to_shared(sdst);
    asm volatile("cp.async.cg.shared.global [%0], [%1], 16;" :: "r"(s), "l"(gsrc));
}
__device__ __forceinline__ void ldsm4(uint32_t* r, uint32_t saddr) {
    asm volatile("ldmatrix.sync.aligned.m8n8.x4.shared.b16 {%0,%1,%2,%3}, [%4];"
        : "=r"(r[0]), "=r"(r[1]), "=r"(r[2]), "=r"(r[3]) : "r"(saddr));
}
__device__ __forceinline__ void mma16816(float* c, const uint32_t* a,
                                         uint32_t b0, uint32_t b1) {
    asm volatile("mma.sync.aligned.m16n8k16.row.col.f32.f16.f16.f32 "
        "{%0,%1,%2,%3}, {%4,%5,%6,%7}, {%8,%9}, {%0,%1,%2,%3};"
        : "+f"(c[0]), "+f"(c[1]), "+f"(c[2]), "+f"(c[3])
        : "r"(a[0]), "r"(a[1]), "r"(a[2]), "r"(a[3]), "r"(b0), "r"(b1));
}
__device__ __forceinline__ void mma16816h(uint32_t* c, const uint32_t* a,
                                          uint32_t b0, uint32_t b1) {
    asm volatile("mma.sync.aligned.m16n8k16.row.col.f16.f16.f16.f16 "
        "{%0,%1}, {%2,%3,%4,%5}, {%6,%7}, {%0,%1};"
        : "+r"(c[0]), "+r"(c[1])
        : "r"(a[0]), "r"(a[1]), "r"(a[2]), "r"(a[3]), "r"(b0), "r"(b1));
}
__device__ __forceinline__ float sspf(float x) {
    if (x > 15.f) return x - 0.69314718055994531f;
    return __logf(1.f + __expf(x)) - 0.69314718055994531f;
}
__device__ __forceinline__ uint32_t smem_u32(const void* p) {
    return (uint32_t)__cvta_generic_to_shared(p);
}
__device__ __forceinline__ void mbar_wait(uint32_t mb, uint32_t parity) {
    uint32_t done;
    asm volatile("{\n\t.reg .pred p;\n\t"
        "mbarrier.try_wait.parity.acquire.cta.shared::cta.b64 p, [%1], %2;\n\t"
        "selp.b32 %0, 1, 0, p;\n\t}"
        : "=r"(done) : "r"(mb), "r"(parity) : "memory");
    if (!done) {
        asm volatile("{\n\t.reg .pred P1;\n\t"
            "W_%=:\n\t"
            "mbarrier.try_wait.parity.acquire.cta.shared::cta.b64 P1, [%0], %1, 0x989680;\n\t"
            "@P1 bra.uni D_%=;\n\t"
            "bra.uni W_%=;\n\t"
            "D_%=:\n\t}"
            :: "r"(mb), "r"(parity) : "memory");
    }
}

// 2-product GEMM, m32n32 warp tile, software-pipelined k-loop. (shared by
// k_main and k_init's embed blocks)
template<int KSTEPS>
__device__ __forceinline__ void mm(uint32_t aBase, uint32_t wBase,
                                   float (&acc)[8][4], uint32_t (&accL)[8][2],
                                   int lw, int lane) {
    const int warp_m = (lw >> 2) & 1, warp_n = lw & 3;
    const int rsel = lane & 15, hsel = lane >> 4;
    uint32_t aAddr = aBase + (uint32_t)(((warp_m*32 + rsel) * PITCH + hsel*8) * 2);
    uint32_t wAddr = wBase + (uint32_t)(((warp_n*32 + rsel) * PITCH + hsel*8) * 2);
    const uint32_t STEP16 = 16 * PITCH * 2;

    uint32_t A[2][2][4], Wh[2][2][4], Wl[2][2][4];   // [buf][frag][reg]
    ldsm4(A[0][0],  aAddr);
    ldsm4(A[0][1],  aAddr + STEP16);
    ldsm4(Wh[0][0], wAddr);
    ldsm4(Wh[0][1], wAddr + STEP16);
    ldsm4(Wl[0][0], wAddr + IMG_W);
    ldsm4(Wl[0][1], wAddr + IMG_W + STEP16);

    #pragma unroll
    for (int kk = 0; kk < KSTEPS; kk++) {
        const int cur = kk & 1, nxt = cur ^ 1;
        if (kk + 1 < KSTEPS) {
            uint32_t ak = aAddr + (kk + 1) * 32;
            uint32_t wk = wAddr + (kk + 1) * 32;
            ldsm4(A[nxt][0],  ak);
            ldsm4(A[nxt][1],  ak + STEP16);
            ldsm4(Wh[nxt][0], wk);
            ldsm4(Wh[nxt][1], wk + STEP16);
            ldsm4(Wl[nxt][0], wk + IMG_W);
            ldsm4(Wl[nxt][1], wk + IMG_W + STEP16);
        }
        #pragma unroll
        for (int mt = 0; mt < 2; mt++)
            #pragma unroll
            for (int q = 0; q < 2; q++)
                #pragma unroll
                for (int j = 0; j < 2; j++) {
                    int t = mt*4 + q*2 + j;
                    mma16816(acc[t],  A[cur][mt], Wh[cur][q][j], Wh[cur][q][j+2]);
                    mma16816h(accL[t], A[cur][mt], Wl[cur][q][j], Wl[cur][q][j+2]);
                }
    }
}

// ---------------- kernel: weight prep (blocks 0-6) + HMMA embed (7-22) -----
__global__ void __launch_bounds__(256) k_init(
    const float* fW1, const float* fW2, const float* f2oW,
    const float* pW1, const float* pW2, const float* eW1, const float* eW2,
    const float* __restrict__ xi, const float* __restrict__ in2f_W) {
    extern __shared__ char sdyn[];
    int bid = blockIdx.x;
    int tid = threadIdx.x;
    if (bid < 7) {
        const float* W; int K, realK;
        switch (bid) {
            case 0: W = fW1;  K = 64;  realK = NSB; break;
            case 1: W = fW2;  K = 128; realK = 128; break;
            case 2: W = f2oW; K = 128; realK = 128; break;
            case 3: W = pW1;  K = 128; realK = 128; break;
            case 4: W = pW2;  K = 128; realK = 128; break;
            case 5: W = eW1;  K = 128; realK = 128; break;
            default: W = eW2; K = 128; realK = 128; break;
        }
        __half* hi = d_wsplit + (size_t)bid * 2 * 128 * PITCH;
        __half* lo = hi + 128 * PITCH;
        for (int i = tid; i < 128 * K; i += 256) {
            int n = i / K, k = i - (i / K) * K;
            float v = (k < realK) ? W[k * 128 + n] : 0.f;   // B^T: [n][k]
            __half h = __float2half_rn(v);
            hi[n * PITCH + k] = h;
            lo[n * PITCH + k] = __float2half_rn(v - __half2float(h));
        }
    } else {
        // HMMA embed: 64 rows per block; d_y = xi @ in2f_W (fp16 2-product)
        const int row0 = (bid - 7) * 64;
        __half* Ah = reinterpret_cast<__half*>(sdyn);
        __half* Wh = reinterpret_cast<__half*>(sdyn + IMG_A);
        __half* Wl = Wh + 128 * PITCH;   // byte offset IMG_W from Wh
        for (int i = tid; i < 64 * 128; i += 256) {
            int r = i >> 7, c = i & 127;
            Ah[r * PITCH + c] = __float2half_rn(xi[(size_t)(row0 + r) * 128 + c]);
        }
        for (int i = tid; i < 128 * 128; i += 256) {
            int k = i >> 7, n = i & 127;
            float v = __ldg(in2f_W + i);           // in2f_W[k][n]
            __half h = __float2half_rn(v);
            Wh[n * PITCH + k] = h;
            Wl[n * PITCH + k] = __float2half_rn(v - __half2float(h));
        }
        __syncthreads();

        float acc[8][4];
        uint32_t accL[8][2];
        #pragma unroll
        for (int t = 0; t < 8; t++) {
            #pragma unroll
            for (int j = 0; j < 4; j++) acc[t][j] = 0.f;
            accL[t][0] = 0u; accL[t][1] = 0u;
        }
        const uint32_t sbi = smem_u32(sdyn);
        const int lw = tid >> 5, lane = tid & 31;
        mm<8>(sbi, sbi + IMG_A, acc, accL, lw, lane);

        const int warp_m = (lw >> 2) & 1, warp_n = lw & 3;
        const int er = lane >> 2, ec2 = (lane & 3) * 2;
        #pragma unroll
        for (int mt = 0; mt < 2; mt++)
            #pragma unroll
            for (int nt = 0; nt < 4; nt++) {
                int t = mt*4 + nt;
                int col = warp_n*32 + nt*8 + ec2;
                #pragma unroll
                for (int h = 0; h < 2; h++) {
                    int row = warp_m*32 + mt*16 + er + h*8;
                    __half2 lo2 = *reinterpret_cast<__half2*>(&accL[t][h]);
                    float x0 = acc[t][h*2+0] + __half2float(lo2.x);
                    float x1 = acc[t][h*2+1] + __half2float(lo2.y);
                    *reinterpret_cast<float2*>(
                        d_y + (size_t)(row0 + row) * 128 + col) = make_float2(x0, x1);
                }
            }
    }
}

// stage epilogue for one pipeline (m32n32 tile mapping)
__device__ __forceinline__ void epilogue(
    int s, float (&acc)[8][4], uint32_t (&accL)[8][2], char* smem, int pid, int ba0,
    int lw, int lane, const float (*sBias)[128],
    const float* sCut, const int* sNbr)
{
    const int warp_m = (lw >> 2) & 1, warp_n = lw & 3;
    const int er = lane >> 2, ec2 = (lane & 3) * 2;
    char* atomBase = smem + pid * ATOM_BLK;
    char* dstH = atomBase + ((s == 2) ? IMG_A : 0);
    float* vikT = reinterpret_cast<float*>(smem + W1_OFF + pid * IMG_W);
    const int baG = ba0 + pid;
    const int bA = baG >> 8;
    #pragma unroll
    for (int mt = 0; mt < 2; mt++) {
        #pragma unroll
        for (int nt = 0; nt < 4; nt++) {
            int t = mt*4 + nt;
            int col = warp_n*32 + nt*8 + ec2;
            float b0 = sBias[s][col], b1 = sBias[s][col + 1];
            #pragma unroll
            for (int h = 0; h < 2; h++) {
                int row = warp_m*32 + mt*16 + er + h*8;   // 0..63
                int grow = pid*64 + row;
                __half2 lo2 = *reinterpret_cast<__half2*>(&accL[t][h]);
                float x0 = acc[t][h*2+0] + __half2float(lo2.x) + b0;
                float x1 = acc[t][h*2+1] + __half2float(lo2.y) + b1;
                if (s == 1) {
                    float cu = sCut[grow];
                    const float2 y = *reinterpret_cast<const float2*>(
                        d_y + ((size_t)((bA << 8) + sNbr[grow]) << 7) + col);
                    x0 = x0 * cu * y.x;
                    x1 = x1 * cu * y.y;
                } else if (s == 4) {
                    *reinterpret_cast<float2*>(
                        d_vij + ((size_t)baG * 64 + row) * 128 + col) =
                        make_float2(x0, x1);
                    continue;
                } else if (s == 6) {
                    vikT[col * VPITCH + row]       = x0;
                    vikT[(col + 1) * VPITCH + row] = x1;
                    continue;
                } else {
                    x0 = sspf(x0); x1 = sspf(x1);
                }
                __half2 hp = __floats2half2_rn(x0, x1);
                uint32_t off = (uint32_t)(row * PITCH + col) * 2;
                *reinterpret_cast<uint32_t*>(dstH + off) = *reinterpret_cast<uint32_t*>(&hp);
            }
        }
    }
}

// ---------------- kernel: fused interaction, double-buffered W -------------
__global__ void __launch_bounds__(512, 1) k_main(
    const float* __restrict__ r_ij, const float* __restrict__ cos_ij,
    const float* __restrict__ f_ij, const float* __restrict__ nmask,
    const float* __restrict__ fb1, const float* __restrict__ fb2,
    const float* __restrict__ f2ob,
    const float* __restrict__ aW1, const float* __restrict__ ab1,
    const float* __restrict__ aW2, const float* __restrict__ ab2,
    const float* __restrict__ pb1, const float* __restrict__ pb2,
    const float* __restrict__ eb1, const float* __restrict__ eb2,
    const int* __restrict__ neighbors, float* __restrict__ out_vi)
{
    extern __shared__ char smem[];
    const uint32_t sb = smem_u32(smem);
    const int tid = threadIdx.x;
    const int pid = tid >> 8;            // pipeline/atom: 0 or 1
    const int lt  = tid & 255, lw = lt >> 5, lane = tid & 31;
    const int ba0 = blockIdx.x * 2;

    __shared__ float sCut[128], sMask[128], cmS[384], vsumS[256], hidS[256];
    __shared__ float sBias[7][128];
    __shared__ int   sNbr[128];
    __shared__ __align__(8) uint64_t mbarW[2];
    const uint32_t mbar0 = smem_u32(&mbarW[0]);
    const uint32_t mbar1 = smem_u32(&mbarW[1]);

    if (tid == 0) {
        asm volatile("mbarrier.init.shared.b64 [%0], %1;" :: "r"(mbar0), "r"(512u) : "memory");
        asm volatile("mbarrier.init.shared.b64 [%0], %1;" :: "r"(mbar1), "r"(512u) : "memory");
    }

    {   // biases to smem
        const float* bp[7] = {fb1, fb2, f2ob, pb1, pb2, eb1, eb2};
        for (int i = tid; i < 7*128; i += 512)
            sBias[i >> 7][i & 127] = __ldg(bp[i >> 7] + (i & 127));
    }
    if (tid < 128) {
        int g = ba0 * NN + tid;
        float r = r_ij[g];
        sCut[tid]  = (r < 5.f) ? 0.5f * (__cosf(r * 0.62831853071795864f) + 1.f) : 0.f;
        float m = nmask[g];
        sMask[tid] = m;
        sNbr[tid]  = neighbors[g];
        cmS[tid*3+0] = cos_ij[(size_t)g*3+0] * m;
        cmS[tid*3+1] = cos_ij[(size_t)g*3+1] * m;
        cmS[tid*3+2] = cos_ij[(size_t)g*3+2] * m;
    }
    {   // zero both atoms' images
        uint64_t* z = reinterpret_cast<uint64_t*>(smem);
        for (int i = tid; i < (2*ATOM_BLK)/8; i += 512) z[i] = 0ull;
    }
    __syncthreads();   // mbar init + zero visible

    {   // issue W(0) -> buf0
        const char* src = reinterpret_cast<const char*>(d_wsplit);
        for (int i = tid * 16; i < WBUF; i += 512*16)
            cp16(smem + W0_OFF + i, src + i);
        asm volatile("cp.async.mbarrier.arrive.noinc.shared.b64 [%0];"
                     :: "r"(mbar0) : "memory");
    }
    {   // scatter features (fp16)
        const float* fg = f_ij + (size_t)(ba0 + pid) * NN * NSB;
        __half* ah = reinterpret_cast<__half*>(smem + pid * ATOM_BLK);
        for (int i = lt; i < NN * NSB; i += 256) {
            int r = i / NSB, c = i - (i / NSB) * NSB;
            ah[r * PITCH + c] = __float2half_rn(fg[i]);
        }
    }
    __syncthreads();   // feature images ready

    float acc[8][4];
    uint32_t accL[8][2];

    for (int s = 0; s < 7; s++) {
        // issue W(s+1) into the other buffer — a full stage of lead
        if (s < 6) {
            const char* src = reinterpret_cast<const char*>(
                d_wsplit + (size_t)(s + 1) * 2 * 128 * PITCH);
            uint32_t woff = ((s + 1) & 1) ? W1_OFF : W0_OFF;
            for (int i = tid * 16; i < WBUF; i += 512*16)
                cp16(smem + woff + i, src + i);
            asm volatile("cp.async.mbarrier.arrive.noinc.shared.b64 [%0];"
                         :: "r"(((s + 1) & 1) ? mbar1 : mbar0) : "memory");
        }

        // Q: epilogue of previous stage overlaps P's MMAs
        if (pid == 1 && s > 0) {
            epilogue(s - 1, acc, accL, smem, 1, ba0, lw, lane, sBias, sCut, sNbr);
            asm volatile("bar.sync 2, 256;" ::: "memory");   // Q-internal
        }
        #pragma unroll
        for (int t = 0; t < 8; t++) {
            #pragma unroll
            for (int j = 0; j < 4; j++) acc[t][j] = 0.f;
            accL[t][0] = 0u; accL[t][1] = 0u;
        }

        mbar_wait((s & 1) ? mbar1 : mbar0, (uint32_t)((s >> 1) & 1));

        uint32_t aBase = sb + pid * ATOM_BLK + ((s == 3 || s == 5) ? IMG_A : 0);
        uint32_t wBase = sb + ((s & 1) ? W1_OFF : W0_OFF);
        if (s == 0) mm<4>(aBase, wBase, acc, accL, lw, lane);
        else        mm<8>(aBase, wBase, acc, accL, lw, lane);

        // P: epilogue overlaps Q's MMAs
        if (pid == 0 && s < 6)
            epilogue(s, acc, accL, smem, 0, ba0, lw, lane, sBias, sCut, sNbr);

        __syncthreads();
    }

    // stage-6 epilogues (both pipelines) -> vikT in W1 buffer
    epilogue(6, acc, accL, smem, pid, ba0, lw, lane, sBias, sCut, sNbr);
    __syncthreads();

    // ---- Vik[c][d] = sum_n vik[n][c] * cm[n][d] (both atoms) ----
    for (int e = tid; e < 768; e += 512) {
        int atom = e / 384, rem = e - atom * 384;
        int c = rem / 3, d = rem - 3 * (rem / 3);
        const float* vikT = reinterpret_cast<const float*>(smem + W1_OFF + atom * IMG_W);
        float s = 0.f;
        #pragma unroll 4
        for (int n = 0; n < 64; n++)
            s = fmaf(vikT[c * VPITCH + n], cmS[(atom*64 + n) * 3 + d], s);
        d_Vik[(size_t)(ba0 + atom) * 384 + rem] = s;
    }

    // ---- vsum from V (fp16 image), atom MLP -> out_vi ----
    if (tid < 256) {
        int atom = tid >> 7, c = tid & 127;
        const __half* vh = reinterpret_cast<const __half*>(smem + atom*ATOM_BLK + IMG_A);
        float s = 0.f;
        #pragma unroll 4
        for (int n = 0; n < 64; n++)
            s = fmaf(__half2float(vh[n * PITCH + c]), sMask[atom*64 + n], s);
        vsumS[tid] = s;
    }
    __syncthreads();
    if (tid < 256) {
        int atom = tid >> 7, c = tid & 127;
        float h = __ldg(ab1 + c);
        #pragma unroll 4
        for (int k = 0; k < 128; k++)
            h = fmaf(vsumS[atom*128 + k], __ldg(aW1 + k * 128 + c), h);
        hidS[tid] = sspf(h);
    }
    __syncthreads();
    if (tid < 256) {
        int atom = tid >> 7, c = tid & 127;
        float o = __ldg(ab2 + c);
        #pragma unroll 4
        for (int k = 0; k < 128; k++)
            o = fmaf(hidS[atom*128 + k], __ldg(aW2 + k * 128 + c), o);
        out_vi[(size_t)(ba0 + atom) * NF + c] = o;
    }
}

// ---------------- kernel: assemble V (warp per idx, 12 floats/lane) --------
__global__ void __launch_bounds__(256) k_assemble(
    const float* __restrict__ cos_ij,
    const int* __restrict__ neighbors,
    float* __restrict__ outV) {
    int idx  = blockIdx.x * 8 + (threadIdx.x >> 5);   // (b,a,n) flat
    int lane = threadIdx.x & 31;
    int ba   = idx >> 6;
    int b    = idx >> 14;
    int nb   = __ldg(neighbors + idx);
    int e0   = lane * 12;

    const float* vikL = d_Vik + (size_t)ba * 384 + e0;
    const float* vikN = d_Vik + ((size_t)(b * AA + nb)) * 384 + e0;
    float4 l0 = *reinterpret_cast<const float4*>(vikL);
    float4 l1 = *reinterpret_cast<const float4*>(vikL + 4);
    float4 l2 = *reinterpret_cast<const float4*>(vikL + 8);
    float4 n0 = *reinterpret_cast<const float4*>(vikN);
    float4 n1 = *reinterpret_cast<const float4*>(vikN + 4);
    float4 n2 = *reinterpret_cast<const float4*>(vikN + 8);
    float4 vij4 = __ldg(reinterpret_cast<const float4*>(d_vij + (size_t)idx * 128) + lane);
    float cc0 = __ldg(cos_ij + (size_t)idx * 3 + 0);
    float cc1 = __ldg(cos_ij + (size_t)idx * 3 + 1);
    float cc2 = __ldg(cos_ij + (size_t)idx * 3 + 2);

    float vs[12] = {l0.x+n0.x, l0.y+n0.y, l0.z+n0.z, l0.w+n0.w,
                    l1.x+n1.x, l1.y+n1.y, l1.z+n1.z, l1.w+n1.w,
                    l2.x+n2.x, l2.y+n2.y, l2.z+n2.z, l2.w+n2.w};
    float vij[4] = {vij4.x, vij4.y, vij4.z, vij4.w};
    float cc[3]  = {cc0, cc1, cc2};
    float o[12];
    #pragma unroll
    for (int j = 0; j < 12; j++) {
        int c = j / 3, d = j - 3 * c;
        o[j] = fmaf(vij[c], cc[d], vs[j]);
    }
    float* dst = outV + (size_t)idx * 384 + e0;
    *reinterpret_cast<float4*>(dst)     = make_float4(o[0], o[1], o[2],  o[3]);
    *reinterpret_cast<float4*>(dst + 4) = make_float4(o[4], o[5], o[6],  o[7]);
    *reinterpret_cast<float4*>(dst + 8) = make_float4(o[8], o[9], o[10], o[11]);
}

// ---------------- launch ----------------
extern "C" void kernel_launch(void* const* d_in, const int* in_sizes, int n_in,
                              void* d_out, int out_size) {
    const float* xi       = (const float*)d_in[0];
    const float* r_ij     = (const float*)d_in[1];
    const float* cos_ij   = (const float*)d_in[2];
    const float* f_ij     = (const float*)d_in[3];
    const float* nmask    = (const float*)d_in[4];
    const float* fW1      = (const float*)d_in[5];
    const float* fb1      = (const float*)d_in[6];
    const float* fW2      = (const float*)d_in[7];
    const float* fb2      = (const float*)d_in[8];
    const float* in2f_W   = (const float*)d_in[9];
    const float* f2oW     = (const float*)d_in[10];
    const float* f2ob     = (const float*)d_in[11];
    const float* aW1      = (const float*)d_in[12];
    const float* ab1      = (const float*)d_in[13];
    const float* aW2      = (const float*)d_in[14];
    const float* ab2      = (const float*)d_in[15];
    const float* pW1      = (const float*)d_in[16];
    const float* pb1      = (const float*)d_in[17];
    const float* pW2      = (const float*)d_in[18];
    const float* pb2      = (const float*)d_in[19];
    const float* eW1      = (const float*)d_in[20];
    const float* eb1      = (const float*)d_in[21];
    const float* eW2      = (const float*)d_in[22];
    const float* eb2      = (const float*)d_in[23];
    const int*   neighbors= (const int*)d_in[24];

    float* out = (float*)d_out;
    float* out_vi = out;                          // [B,A,NCB]
    float* out_V  = out + (size_t)BB*AA*NCB;      // [B,A,N,NCB,3]

    cudaFuncSetAttribute(k_init, cudaFuncAttributeMaxDynamicSharedMemorySize,
                         (int)INIT_SMEM);
    cudaFuncSetAttribute(k_main, cudaFuncAttributeMaxDynamicSharedMemorySize,
                         (int)SMEM_BYTES);

    k_init<<<7 + BB*AA/64, 256, INIT_SMEM>>>(fW1, fW2, f2oW, pW1, pW2, eW1, eW2, xi, in2f_W);
    k_main<<<BB*AA/2, 512, SMEM_BYTES>>>(
        r_ij, cos_ij, f_ij, nmask,
        fb1, fb2, f2ob, aW1, ab1, aW2, ab2,
        pb1, pb2, eb1, eb2, neighbors, out_vi);
    k_assemble<<<BB*AA*NN/8, 256>>>(cos_ij, neighbors, out_V);
}